// round 4
// baseline (speedup 1.0000x reference)
#include <cuda_runtime.h>
#include <math.h>

#define D_DIM 128
#define N_NODES 50000
#define N_EDGES 600000
#define LN_EPS 1e-5f
#define TILE_ROWS 64

typedef unsigned long long u64;

// Scratch (allocation-free rule: __device__ globals)
__device__ float g_hpre[N_NODES * D_DIM];
__device__ float g_agg [N_NODES * D_DIM];
__device__ float g_t1  [N_NODES * D_DIM];

// Packed 2xfp32 FMA (Blackwell FFMA2 — only reachable via PTX)
__device__ __forceinline__ u64 fma2(u64 a, u64 b, u64 c) {
    u64 d;
    asm("fma.rn.f32x2 %0, %1, %2, %3;" : "=l"(d) : "l"(a), "l"(b), "l"(c));
    return d;
}
__device__ __forceinline__ float hadd2(u64 v) {
    float a, b;
    asm("mov.b64 {%0, %1}, %2;" : "=f"(a), "=f"(b) : "l"(v));
    return a + b;
}
// SW128 swizzle on byte offsets within a 1024B block
__device__ __forceinline__ int swz(int byte_off) {
    return byte_off ^ ((byte_off >> 3) & 0x70);
}

// ---------------------------------------------------------------------------
// Edge scatter: one warp per edge. agg[dst] += hpre[src] via red.global.v4
// ---------------------------------------------------------------------------
__global__ void scatter_kernel(const float* __restrict__ hpre,
                               const int* __restrict__ src,
                               const int* __restrict__ dst,
                               float* __restrict__ agg) {
    int gid  = blockIdx.x * blockDim.x + threadIdx.x;
    int e    = gid >> 5;
    int lane = gid & 31;
    if (e >= N_EDGES) return;
    int s = src[e];
    int d = dst[e];
    float4 v = ((const float4*)(hpre + (size_t)s * D_DIM))[lane];
    float* o = agg + (size_t)d * D_DIM + lane * 4;
    asm volatile("red.global.add.v4.f32 [%0], {%1, %2, %3, %4};"
                 :: "l"(o), "f"(v.x), "f"(v.y), "f"(v.z), "f"(v.w)
                 : "memory");
}

// ---------------------------------------------------------------------------
// GEMM: out[nrows,128] = act(A[nrows,128] @ W[128,128] + bias)
// MODE 0: plain store (+ optional zbuf zeroing fused)
// MODE 1: relu store
// MODE 2: v = resid + relu(A@W + bias); out = LayerNorm(v)*gamma + beta
//
// 256 threads, 64-row tile. W staged into smem k-pair-interleaved + SW128
// swizzled; inner loop uses fma.rn.f32x2 (2 FMAs/instr). Thread = 8 rows x
// 4 cols; accumulators are f32x2 over (even-k, odd-k) partial sums.
// ---------------------------------------------------------------------------
template <int MODE>
__global__ void __launch_bounds__(256, 2)
gemm_kernel(const float* __restrict__ A, const float* __restrict__ W,
            const float* __restrict__ bias, const float* __restrict__ resid,
            const float* __restrict__ gamma, const float* __restrict__ beta,
            float* __restrict__ out, float* __restrict__ zbuf, int nrows) {
    extern __shared__ float smem[];
    float* sWp = smem;                    // 64KB: 64 pair-blocks x 1024B
    float* sA  = smem + D_DIM * D_DIM;    // 32KB: 64 rows x 128 floats

    const int tid  = threadIdx.x;
    const int base = blockIdx.x * TILE_ROWS;

    // ---- Stage W k-pair interleaved with SW128 swizzle ----
    // Unswizzled layout of pair-block p (1024B): for col group cg (lane),
    // bytes [cg*32, cg*32+32) hold 4 col-pairs:
    //   (W[2p][4cg],W[2p+1][4cg]) (W[2p][4cg+1],W[2p+1][4cg+1]) ...
    {
        const float4* W4 = (const float4*)W;
        #pragma unroll
        for (int i = tid; i < 64 * 32; i += 256) {
            int p  = i >> 5;
            int cg = i & 31;
            float4 r0 = W4[(size_t)(2 * p)     * 32 + cg];
            float4 r1 = W4[(size_t)(2 * p + 1) * 32 + cg];
            char* blk = (char*)sWp + p * 1024;
            *(float4*)(blk + swz(cg * 32))      = make_float4(r0.x, r1.x, r0.y, r1.y);
            *(float4*)(blk + swz(cg * 32 + 16)) = make_float4(r0.z, r1.z, r0.w, r1.w);
        }
    }
    // ---- Stage A tile (row-major, natural: k-pairs are contiguous) ----
    {
        const float4* A4 = (const float4*)A;
        float4* sA4 = (float4*)sA;
        #pragma unroll
        for (int i = tid; i < (TILE_ROWS * D_DIM) / 4; i += 256) {
            int r   = i >> 5;
            int row = base + r;
            sA4[i] = (row < nrows) ? A4[(size_t)row * 32 + (i & 31)]
                                   : make_float4(0.f, 0.f, 0.f, 0.f);
        }
    }
    __syncthreads();

    const int cg = tid & 31;   // lane: cols 4cg .. 4cg+3
    const int rg = tid >> 5;   // warp: rows rg*8 .. rg*8+7
    const int rowbase = rg * 8;

    // Precomputed swizzled per-lane W offsets (constant across pair-blocks)
    const int off0 = swz(cg * 32);
    const int off1 = swz(cg * 32 + 16);
    const char* wb = (const char*)sWp;
    const ulonglong2* sA2 = (const ulonglong2*)sA;  // 32 per row (512B/16B)

    u64 acc[8][4];
    #pragma unroll
    for (int r = 0; r < 8; r++)
        #pragma unroll
        for (int c = 0; c < 4; c++) acc[r][c] = 0ull;

    // t iterates 16B A-chunks: 4 k values = pairs p0=2t, p1=2t+1
    #pragma unroll 2
    for (int t = 0; t < 32; t++) {
        const char* b0 = wb + (size_t)(2 * t)     * 1024;
        const char* b1 = wb + (size_t)(2 * t + 1) * 1024;
        ulonglong2 wA0 = *(const ulonglong2*)(b0 + off0);  // p0: cols c0,c1
        ulonglong2 wA1 = *(const ulonglong2*)(b0 + off1);  // p0: cols c2,c3
        ulonglong2 wB0 = *(const ulonglong2*)(b1 + off0);  // p1: cols c0,c1
        ulonglong2 wB1 = *(const ulonglong2*)(b1 + off1);  // p1: cols c2,c3
        #pragma unroll
        for (int r = 0; r < 8; r++) {
            ulonglong2 ap = sA2[(size_t)(rowbase + r) * 32 + t];  // broadcast
            acc[r][0] = fma2(ap.x, wA0.x, acc[r][0]);
            acc[r][1] = fma2(ap.x, wA0.y, acc[r][1]);
            acc[r][2] = fma2(ap.x, wA1.x, acc[r][2]);
            acc[r][3] = fma2(ap.x, wA1.y, acc[r][3]);
            acc[r][0] = fma2(ap.y, wB0.x, acc[r][0]);
            acc[r][1] = fma2(ap.y, wB0.y, acc[r][1]);
            acc[r][2] = fma2(ap.y, wB1.x, acc[r][2]);
            acc[r][3] = fma2(ap.y, wB1.y, acc[r][3]);
        }
    }

    // Reduce pairs, add bias (+relu)
    float4 b = ((const float4*)bias)[cg];
    float4 res[8];
    #pragma unroll
    for (int r = 0; r < 8; r++) {
        float4 v;
        v.x = hadd2(acc[r][0]) + b.x;
        v.y = hadd2(acc[r][1]) + b.y;
        v.z = hadd2(acc[r][2]) + b.z;
        v.w = hadd2(acc[r][3]) + b.w;
        if (MODE >= 1) {
            v.x = fmaxf(v.x, 0.f); v.y = fmaxf(v.y, 0.f);
            v.z = fmaxf(v.z, 0.f); v.w = fmaxf(v.w, 0.f);
        }
        res[r] = v;
    }

    float4* out4 = (float4*)out;

    if (MODE < 2) {
        #pragma unroll
        for (int r = 0; r < 8; r++) {
            int row = base + rowbase + r;
            if (row < nrows) out4[(size_t)row * 32 + cg] = res[r];
        }
        // Fused zeroing of the aggregation buffer (hidden under compute)
        if (zbuf) {
            float4* z4 = (float4*)zbuf;
            #pragma unroll
            for (int r = 0; r < 8; r++) {
                int row = base + rowbase + r;
                if (row < nrows)
                    z4[(size_t)row * 32 + cg] = make_float4(0.f, 0.f, 0.f, 0.f);
            }
        }
        return;
    }

    // MODE 2: residual + LayerNorm, registers + warp shuffles only.
    const float4* res4g = (const float4*)resid;
    float4 gm = ((const float4*)gamma)[cg];
    float4 bt = ((const float4*)beta)[cg];
    #pragma unroll
    for (int r = 0; r < 8; r++) {
        int row = base + rowbase + r;
        float4 rr = (row < nrows) ? res4g[(size_t)row * 32 + cg]
                                  : make_float4(0.f, 0.f, 0.f, 0.f);
        float4 v;
        v.x = res[r].x + rr.x; v.y = res[r].y + rr.y;
        v.z = res[r].z + rr.z; v.w = res[r].w + rr.w;
        float s  = v.x + v.y + v.z + v.w;
        float s2 = v.x * v.x + v.y * v.y + v.z * v.z + v.w * v.w;
        #pragma unroll
        for (int off = 16; off > 0; off >>= 1) {
            s  += __shfl_xor_sync(0xFFFFFFFFu, s,  off);
            s2 += __shfl_xor_sync(0xFFFFFFFFu, s2, off);
        }
        float mean = s * (1.0f / D_DIM);
        float var  = s2 * (1.0f / D_DIM) - mean * mean;
        float rstd = rsqrtf(var + LN_EPS);
        float4 o;
        o.x = (v.x - mean) * rstd * gm.x + bt.x;
        o.y = (v.y - mean) * rstd * gm.y + bt.y;
        o.z = (v.z - mean) * rstd * gm.z + bt.z;
        o.w = (v.w - mean) * rstd * gm.w + bt.w;
        if (row < nrows) out4[(size_t)row * 32 + cg] = o;
    }
}

// ---------------------------------------------------------------------------
extern "C" void kernel_launch(void* const* d_in, const int* in_sizes, int n_in,
                              void* d_out, int out_size) {
    const float* h     = (const float*)d_in[0];
    const int*   src   = (const int*)  d_in[1];
    const int*   dst   = (const int*)  d_in[2];
    const float* W_pre = (const float*)d_in[3];
    const float* b_pre = (const float*)d_in[4];
    const float* W1    = (const float*)d_in[5];
    const float* b1    = (const float*)d_in[6];
    const float* W2    = (const float*)d_in[7];
    const float* b2    = (const float*)d_in[8];
    const float* gamma = (const float*)d_in[9];
    const float* beta  = (const float*)d_in[10];
    float* out = (float*)d_out;

    float *hpre, *agg, *t1;
    cudaGetSymbolAddress((void**)&hpre, g_hpre);
    cudaGetSymbolAddress((void**)&agg,  g_agg);
    cudaGetSymbolAddress((void**)&t1,   g_t1);

    const int smem_bytes = (D_DIM * D_DIM + TILE_ROWS * D_DIM) * sizeof(float); // 96KB
    cudaFuncSetAttribute(gemm_kernel<0>, cudaFuncAttributeMaxDynamicSharedMemorySize, smem_bytes);
    cudaFuncSetAttribute(gemm_kernel<1>, cudaFuncAttributeMaxDynamicSharedMemorySize, smem_bytes);
    cudaFuncSetAttribute(gemm_kernel<2>, cudaFuncAttributeMaxDynamicSharedMemorySize, smem_bytes);

    const int gemm_blocks = (N_NODES + TILE_ROWS - 1) / TILE_ROWS;  // 782

    // 1. hpre = h @ W_pre + b_pre   (also zeroes agg, fused)
    gemm_kernel<0><<<gemm_blocks, 256, smem_bytes>>>(h, W_pre, b_pre,
                                                     nullptr, nullptr, nullptr,
                                                     hpre, agg, N_NODES);
    // 2. agg[dst] += hpre[src]  (warp per edge, vectorized red)
    {
        long long threads = (long long)N_EDGES * 32;
        int blocks = (int)((threads + 255) / 256);
        scatter_kernel<<<blocks, 256>>>(hpre, src, dst, agg);
    }
    // 3. t1 = relu(agg @ W1 + b1)
    gemm_kernel<1><<<gemm_blocks, 256, smem_bytes>>>(agg, W1, b1,
                                                     nullptr, nullptr, nullptr,
                                                     t1, nullptr, N_NODES);
    // 4. out = LayerNorm(hpre + relu(t1 @ W2 + b2)) * gamma + beta
    gemm_kernel<2><<<gemm_blocks, 256, smem_bytes>>>(t1, W2, b2,
                                                     hpre, gamma, beta,
                                                     out, nullptr, N_NODES);
    (void)in_sizes; (void)n_in; (void)out_size;
}

// round 6
// speedup vs baseline: 1.0693x; 1.0693x over previous
#include <cuda_runtime.h>
#include <cuda_bf16.h>
#include <math.h>
#include <stdint.h>

#define D_DIM 128
#define N_NODES 50000
#define N_EDGES 600000
#define LN_EPS 1e-5f
#define TILE_M 128

typedef unsigned int u32;

// Scratch (allocation-free rule: __device__ globals)
__device__ float g_hpre[N_NODES * D_DIM];
__device__ float g_agg [N_NODES * D_DIM];
__device__ float g_t1  [N_NODES * D_DIM];

// ---------------- smem layout (bytes) ----------------
// Fragment-major storage, written during staging, read with LDS.128/LDS.64.
// A-frag:  [ks(8)][mi(8)][lane(32)] x 16B  (regs a0..a3)   = 32KB per split
// B-frag:  [ks(8)][ni(16)][lane(32)] x 8B  (regs b0..b1)   = 32KB per split
#define SM_BIAS   0
#define SM_GAMMA  512
#define SM_BETA   1024
#define SM_AHI    2048
#define SM_ALO    (SM_AHI + 32768)
#define SM_BHI    (SM_ALO + 32768)
#define SM_BLO    (SM_BHI + 32768)
#define SMEM_TOTAL (SM_BLO + 32768)   // 133120 bytes

__device__ __forceinline__ u32 pack_bf16x2(__nv_bfloat16 lo, __nv_bfloat16 hi) {
    __nv_bfloat162 v; v.x = lo; v.y = hi;
    return *(u32*)&v;
}
__device__ __forceinline__ void split2(float a, __nv_bfloat16& hi, __nv_bfloat16& lo) {
    hi = __float2bfloat16_rn(a);
    lo = __float2bfloat16_rn(a - __bfloat162float(hi));
}
__device__ __forceinline__ void mma_bf16(float* c, const u32* a, const u32* b) {
    asm volatile(
        "mma.sync.aligned.m16n8k16.row.col.f32.bf16.bf16.f32 "
        "{%0,%1,%2,%3}, {%4,%5,%6,%7}, {%8,%9}, {%0,%1,%2,%3};"
        : "+f"(c[0]), "+f"(c[1]), "+f"(c[2]), "+f"(c[3])
        : "r"(a[0]), "r"(a[1]), "r"(a[2]), "r"(a[3]), "r"(b[0]), "r"(b[1]));
}

// ---------------------------------------------------------------------------
// Edge scatter (proven): warp per edge, red.global.add.v4
// ---------------------------------------------------------------------------
__global__ void scatter_kernel(const float* __restrict__ hpre,
                               const int* __restrict__ src,
                               const int* __restrict__ dst,
                               float* __restrict__ agg) {
    int gid  = blockIdx.x * blockDim.x + threadIdx.x;
    int e    = gid >> 5;
    int lane = gid & 31;
    if (e >= N_EDGES) return;
    int s = src[e];
    int d = dst[e];
    float4 v = ((const float4*)(hpre + (size_t)s * D_DIM))[lane];
    float* o = agg + (size_t)d * D_DIM + lane * 4;
    asm volatile("red.global.add.v4.f32 [%0], {%1, %2, %3, %4};"
                 :: "l"(o), "f"(v.x), "f"(v.y), "f"(v.z), "f"(v.w)
                 : "memory");
}

// ---------------------------------------------------------------------------
// HMMA bf16 split-2 GEMM: 128-row tile = act(A[.,128] @ W[128,128] + bias)
// MODE 0: store (+ fused zbuf zeroing)  MODE 1: relu  MODE 2: +resid, LN
// 256 threads = 8 warps; warp wid owns m-tile rows [wid*16, wid*16+16).
// 3 terms: Ah*Bh + Ah*Bl + Al*Bh, fp32 accumulate in C frags.
// ---------------------------------------------------------------------------
template <int MODE>
__global__ void __launch_bounds__(256, 1)
gemm_hmma(const float* __restrict__ A, const float* __restrict__ W,
          const float* __restrict__ bias, const float* __restrict__ resid,
          const float* __restrict__ gamma, const float* __restrict__ beta,
          float* __restrict__ out, float* __restrict__ zbuf, int nrows) {
    extern __shared__ char smem[];
    const int tid  = threadIdx.x;
    const int wid  = tid >> 5;
    const int lane = tid & 31;
    const int base = blockIdx.x * TILE_M;

    float* bias_s  = (float*)(smem + SM_BIAS);
    float* gamma_s = (float*)(smem + SM_GAMMA);
    float* beta_s  = (float*)(smem + SM_BETA);
    if (tid < 128) {
        bias_s[tid] = bias[tid];
        if (MODE == 2) { gamma_s[tid] = gamma[tid]; beta_s[tid] = beta[tid]; }
    }

    // ---- Stage A -> hi/lo fragments ----
    // element (row, k=2j, 2j+1): mi=row>>4, ks=j>>3,
    // lane=(row&7)*4+(j&3), reg=((j>>2)&1)*2 + ((row>>3)&1), k-pair packs one u32
    {
        const float2* A2 = (const float2*)A;
        #pragma unroll 4
        for (int i = tid; i < 128 * 64; i += 256) {
            int row = i >> 6, j = i & 63;
            float2 a = (base + row < nrows) ? A2[(size_t)(base + row) * 64 + j]
                                            : make_float2(0.f, 0.f);
            __nv_bfloat16 hx, lx, hy, ly;
            split2(a.x, hx, lx);
            split2(a.y, hy, ly);
            int mi = row >> 4, ks = j >> 3;
            int ln = ((row & 7) << 2) | (j & 3);
            int reg = (((j >> 2) & 1) << 1) | ((row >> 3) & 1);
            int off = ((ks * 8 + mi) * 32 + ln) * 16 + reg * 4;
            *(u32*)(smem + SM_AHI + off) = pack_bf16x2(hx, hy);
            *(u32*)(smem + SM_ALO + off) = pack_bf16x2(lx, ly);
        }
    }
    // ---- Stage B = W^T -> hi/lo fragments ----
    // element (k=2j,2j+1, n): ni=n>>3, ks=j>>3,
    // lane=(n&7)*4+(j&3), reg=(j>>2)&1
    {
        #pragma unroll 4
        for (int i = tid; i < 64 * 128; i += 256) {
            int j = i >> 7, n = i & 127;
            float w0 = W[(size_t)(2 * j)     * 128 + n];
            float w1 = W[(size_t)(2 * j + 1) * 128 + n];
            __nv_bfloat16 h0, l0, h1, l1;
            split2(w0, h0, l0);
            split2(w1, h1, l1);
            int ni = n >> 3, ks = j >> 3;
            int ln = ((n & 7) << 2) | (j & 3);
            int reg = (j >> 2) & 1;
            int off = ((ks * 16 + ni) * 32 + ln) * 8 + reg * 4;
            *(u32*)(smem + SM_BHI + off) = pack_bf16x2(h0, h1);
            *(u32*)(smem + SM_BLO + off) = pack_bf16x2(l0, l1);
        }
    }
    __syncthreads();

    // ---- MMA mainloop: warp = m-tile wid; 16 n-tiles x 8 k-steps x 3 terms
    float c[16][4];
    #pragma unroll
    for (int ni = 0; ni < 16; ni++)
        #pragma unroll
        for (int r = 0; r < 4; r++) c[ni][r] = 0.f;

    #pragma unroll
    for (int term = 0; term < 3; term++) {
        const char* aBase = smem + ((term == 2) ? SM_ALO : SM_AHI);
        const char* bBase = smem + ((term == 1) ? SM_BLO : SM_BHI);
        #pragma unroll
        for (int ks = 0; ks < 8; ks++) {
            u32 a[4];
            *(uint4*)a = *(const uint4*)(aBase + ((ks * 8 + wid) * 32 + lane) * 16);
            #pragma unroll
            for (int ni = 0; ni < 16; ni++) {
                u32 b[2];
                *(uint2*)b = *(const uint2*)(bBase + ((ks * 16 + ni) * 32 + lane) * 8);
                mma_bf16(c[ni], a, b);
            }
        }
    }

    // ---- Epilogue (all-register) ----
    // C frag: lane = g*4+t; c0,c1 = row g,  cols 2t,2t+1 of n-tile
    //                       c2,c3 = row g+8, same cols
    const int g = lane >> 2, t = lane & 3;
    const int row0 = base + wid * 16 + g;
    const int row1 = row0 + 8;
    const bool ok0 = row0 < nrows, ok1 = row1 < nrows;
    float2* out2 = (float2*)out;

    if (MODE < 2) {
        #pragma unroll
        for (int ni = 0; ni < 16; ni++) {
            int col = ni * 8 + t * 2;
            float2 b2 = *(const float2*)(bias_s + col);
            float v00 = c[ni][0] + b2.x, v01 = c[ni][1] + b2.y;
            float v10 = c[ni][2] + b2.x, v11 = c[ni][3] + b2.y;
            if (MODE == 1) {
                v00 = fmaxf(v00, 0.f); v01 = fmaxf(v01, 0.f);
                v10 = fmaxf(v10, 0.f); v11 = fmaxf(v11, 0.f);
            }
            if (ok0) out2[(size_t)row0 * 64 + (col >> 1)] = make_float2(v00, v01);
            if (ok1) out2[(size_t)row1 * 64 + (col >> 1)] = make_float2(v10, v11);
        }
        // Fused agg zeroing (MODE 0 only), coalesced
        if (MODE == 0 && zbuf) {
            float4* z4 = (float4*)zbuf;
            #pragma unroll 4
            for (int i = tid; i < 128 * 32; i += 256) {
                int row = i >> 5;
                if (base + row < nrows)
                    z4[(size_t)(base + row) * 32 + (i & 31)] =
                        make_float4(0.f, 0.f, 0.f, 0.f);
            }
        }
        return;
    }

    // MODE 2: v = resid + relu(mma + bias); out = LN(v)*gamma + beta
    const float2* R2 = (const float2*)resid;
    float s0 = 0.f, q0 = 0.f, s1 = 0.f, q1 = 0.f;
    #pragma unroll
    for (int ni = 0; ni < 16; ni++) {
        int col = ni * 8 + t * 2;
        float2 b2 = *(const float2*)(bias_s + col);
        float2 r0 = ok0 ? R2[(size_t)row0 * 64 + (col >> 1)] : make_float2(0.f, 0.f);
        float2 r1 = ok1 ? R2[(size_t)row1 * 64 + (col >> 1)] : make_float2(0.f, 0.f);
        float v00 = fmaxf(c[ni][0] + b2.x, 0.f) + r0.x;
        float v01 = fmaxf(c[ni][1] + b2.y, 0.f) + r0.y;
        float v10 = fmaxf(c[ni][2] + b2.x, 0.f) + r1.x;
        float v11 = fmaxf(c[ni][3] + b2.y, 0.f) + r1.y;
        c[ni][0] = v00; c[ni][1] = v01; c[ni][2] = v10; c[ni][3] = v11;
        s0 += v00 + v01; q0 += v00 * v00 + v01 * v01;
        s1 += v10 + v11; q1 += v10 * v10 + v11 * v11;
    }
    // reduce over the 4-lane quad that shares rows (row0, row1)
    #pragma unroll
    for (int off = 1; off <= 2; off <<= 1) {
        s0 += __shfl_xor_sync(0xFFFFFFFFu, s0, off);
        q0 += __shfl_xor_sync(0xFFFFFFFFu, q0, off);
        s1 += __shfl_xor_sync(0xFFFFFFFFu, s1, off);
        q1 += __shfl_xor_sync(0xFFFFFFFFu, q1, off);
    }
    float mean0 = s0 * (1.0f / D_DIM);
    float mean1 = s1 * (1.0f / D_DIM);
    float rstd0 = rsqrtf(q0 * (1.0f / D_DIM) - mean0 * mean0 + LN_EPS);
    float rstd1 = rsqrtf(q1 * (1.0f / D_DIM) - mean1 * mean1 + LN_EPS);
    #pragma unroll
    for (int ni = 0; ni < 16; ni++) {
        int col = ni * 8 + t * 2;
        float2 g2 = *(const float2*)(gamma_s + col);
        float2 t2 = *(const float2*)(beta_s + col);
        if (ok0) {
            float2 o;
            o.x = (c[ni][0] - mean0) * rstd0 * g2.x + t2.x;
            o.y = (c[ni][1] - mean0) * rstd0 * g2.y + t2.y;
            out2[(size_t)row0 * 64 + (col >> 1)] = o;
        }
        if (ok1) {
            float2 o;
            o.x = (c[ni][2] - mean1) * rstd1 * g2.x + t2.x;
            o.y = (c[ni][3] - mean1) * rstd1 * g2.y + t2.y;
            out2[(size_t)row1 * 64 + (col >> 1)] = o;
        }
    }
}

// ---------------------------------------------------------------------------
extern "C" void kernel_launch(void* const* d_in, const int* in_sizes, int n_in,
                              void* d_out, int out_size) {
    const float* h     = (const float*)d_in[0];
    const int*   src   = (const int*)  d_in[1];
    const int*   dst   = (const int*)  d_in[2];
    const float* W_pre = (const float*)d_in[3];
    const float* b_pre = (const float*)d_in[4];
    const float* W1    = (const float*)d_in[5];
    const float* b1    = (const float*)d_in[6];
    const float* W2    = (const float*)d_in[7];
    const float* b2    = (const float*)d_in[8];
    const float* gamma = (const float*)d_in[9];
    const float* beta  = (const float*)d_in[10];
    float* out = (float*)d_out;

    float *hpre, *agg, *t1;
    cudaGetSymbolAddress((void**)&hpre, g_hpre);
    cudaGetSymbolAddress((void**)&agg,  g_agg);
    cudaGetSymbolAddress((void**)&t1,   g_t1);

    cudaFuncSetAttribute(gemm_hmma<0>, cudaFuncAttributeMaxDynamicSharedMemorySize, SMEM_TOTAL);
    cudaFuncSetAttribute(gemm_hmma<1>, cudaFuncAttributeMaxDynamicSharedMemorySize, SMEM_TOTAL);
    cudaFuncSetAttribute(gemm_hmma<2>, cudaFuncAttributeMaxDynamicSharedMemorySize, SMEM_TOTAL);

    const int blocks = (N_NODES + TILE_M - 1) / TILE_M;  // 391

    // 1. hpre = h @ W_pre + b_pre   (also zeroes agg, fused)
    gemm_hmma<0><<<blocks, 256, SMEM_TOTAL>>>(h, W_pre, b_pre,
                                              nullptr, nullptr, nullptr,
                                              hpre, agg, N_NODES);
    // 2. agg[dst] += hpre[src]
    {
        long long threads = (long long)N_EDGES * 32;
        int nb = (int)((threads + 255) / 256);
        scatter_kernel<<<nb, 256>>>(hpre, src, dst, agg);
    }
    // 3. t1 = relu(agg @ W1 + b1)
    gemm_hmma<1><<<blocks, 256, SMEM_TOTAL>>>(agg, W1, b1,
                                              nullptr, nullptr, nullptr,
                                              t1, nullptr, N_NODES);
    // 4. out = LayerNorm(hpre + relu(t1 @ W2 + b2)) * gamma + beta
    gemm_hmma<2><<<blocks, 256, SMEM_TOTAL>>>(t1, W2, b2,
                                              hpre, gamma, beta,
                                              out, nullptr, N_NODES);
    (void)in_sizes; (void)n_in; (void)out_size;
}

// round 7
// speedup vs baseline: 1.4740x; 1.3785x over previous
#include <cuda_runtime.h>
#include <cuda_bf16.h>
#include <math.h>
#include <stdint.h>

#define D_DIM 128
#define N_NODES 50000
#define N_EDGES 600000
#define LN_EPS 1e-5f
#define TILE_M 128

typedef unsigned int u32;

// Scratch (allocation-free rule: __device__ globals)
__device__ float g_hpre[N_NODES * D_DIM];
__device__ float g_agg [N_NODES * D_DIM];
// Precomputed W fragments: [w][((ks*16+ni)*32+lane)*2 + reg], w=0:W_pre 1:W1 2:W2
__device__ u32 g_bf_hi[3][8192];
__device__ u32 g_bf_lo[3][8192];

// ---------------- smem layout (bytes) ----------------
#define SM_B1     0            // bias (first gemm in kernel)
#define SM_B2     512
#define SM_GAMMA  1024
#define SM_BETA   1536
#define SM_AHI    2048         // A frags [ks8][mi8][lane32] x 16B = 32KB
#define SM_ALO    (SM_AHI + 32768)
#define SMEM_TOTAL (SM_ALO + 32768)   // 67584

__device__ __forceinline__ u32 pack_bf16x2(__nv_bfloat16 lo, __nv_bfloat16 hi) {
    __nv_bfloat162 v; v.x = lo; v.y = hi;
    return *(u32*)&v;
}
__device__ __forceinline__ void split2(float a, __nv_bfloat16& hi, __nv_bfloat16& lo) {
    hi = __float2bfloat16_rn(a);
    lo = __float2bfloat16_rn(a - __bfloat162float(hi));
}
__device__ __forceinline__ void mma_bf16(float* c, const u32* a, const u32* b) {
    asm volatile(
        "mma.sync.aligned.m16n8k16.row.col.f32.bf16.bf16.f32 "
        "{%0,%1,%2,%3}, {%4,%5,%6,%7}, {%8,%9}, {%0,%1,%2,%3};"
        : "+f"(c[0]), "+f"(c[1]), "+f"(c[2]), "+f"(c[3])
        : "r"(a[0]), "r"(a[1]), "r"(a[2]), "r"(a[3]), "r"(b[0]), "r"(b[1]));
}

// ---------------------------------------------------------------------------
// W prep: convert 3 weight matrices into global hi/lo B-fragment arrays.
// grid = 24 (8 parts per matrix), 256 threads.
// ---------------------------------------------------------------------------
__global__ void wprep_kernel(const float* __restrict__ W0,
                             const float* __restrict__ W1,
                             const float* __restrict__ W2) {
    const float* Ws[3] = {W0, W1, W2};
    int w = blockIdx.x >> 3, part = blockIdx.x & 7;
    const float* W = Ws[w];
    u32* bh = g_bf_hi[w];
    u32* bl = g_bf_lo[w];
    // pairs (j, n): j = k-pair 0..63, n = 0..127; 8192 pairs, 1024 per part
    for (int i = part * 1024 + threadIdx.x; i < (part + 1) * 1024; i += 256) {
        int j = i >> 7, n = i & 127;
        float w0 = W[(size_t)(2 * j)     * 128 + n];
        float w1 = W[(size_t)(2 * j + 1) * 128 + n];
        __nv_bfloat16 h0, l0, h1, l1;
        split2(w0, h0, l0);
        split2(w1, h1, l1);
        int ni = n >> 3, ks = j >> 3;
        int ln = ((n & 7) << 2) | (j & 3);
        int reg = (j >> 2) & 1;
        int idx = ((ks * 16 + ni) * 32 + ln) * 2 + reg;
        bh[idx] = pack_bf16x2(h0, h1);
        bl[idx] = pack_bf16x2(l0, l1);
    }
}

// ---------------------------------------------------------------------------
// Edge scatter (proven): warp per edge, red.global.add.v4
// ---------------------------------------------------------------------------
__global__ void scatter_kernel(const float* __restrict__ hpre,
                               const int* __restrict__ src,
                               const int* __restrict__ dst,
                               float* __restrict__ agg) {
    int gid  = blockIdx.x * blockDim.x + threadIdx.x;
    int e    = gid >> 5;
    int lane = gid & 31;
    if (e >= N_EDGES) return;
    int s = src[e];
    int d = dst[e];
    float4 v = ((const float4*)(hpre + (size_t)s * D_DIM))[lane];
    float* o = agg + (size_t)d * D_DIM + lane * 4;
    asm volatile("red.global.add.v4.f32 [%0], {%1, %2, %3, %4};"
                 :: "l"(o), "f"(v.x), "f"(v.y), "f"(v.z), "f"(v.w)
                 : "memory");
}

// ---------------------------------------------------------------------------
// Shared building blocks
// ---------------------------------------------------------------------------
// Stage A[base..base+128) x 128 fp32 -> hi/lo bf16 A-frags in smem.
__device__ __forceinline__ void stage_A(char* smem, const float* __restrict__ A,
                                        int base, int nrows, int tid) {
    const float2* A2 = (const float2*)A;
    #pragma unroll 4
    for (int i = tid; i < 128 * 64; i += 256) {
        int row = i >> 6, j = i & 63;
        float2 a = (base + row < nrows) ? A2[(size_t)(base + row) * 64 + j]
                                        : make_float2(0.f, 0.f);
        __nv_bfloat16 hx, lx, hy, ly;
        split2(a.x, hx, lx);
        split2(a.y, hy, ly);
        int mi = row >> 4, ks = j >> 3;
        int ln = ((row & 7) << 2) | (j & 3);
        int reg = (((j >> 2) & 1) << 1) | ((row >> 3) & 1);
        int off = ((ks * 8 + mi) * 32 + ln) * 16 + reg * 4;
        *(u32*)(smem + SM_AHI + off) = pack_bf16x2(hx, hy);
        *(u32*)(smem + SM_ALO + off) = pack_bf16x2(lx, ly);
    }
}

// Mainloop: c += A(smem frags, m-tile wid) x B(global frags), 3 split terms.
__device__ __forceinline__ void mma_mainloop(const char* smem,
                                             const uint2* __restrict__ bh,
                                             const uint2* __restrict__ bl,
                                             float c[16][4], int wid, int lane) {
    #pragma unroll
    for (int ks = 0; ks < 8; ks++) {
        u32 ah[4], al[4];
        *(uint4*)ah = *(const uint4*)(smem + SM_AHI + ((ks * 8 + wid) * 32 + lane) * 16);
        *(uint4*)al = *(const uint4*)(smem + SM_ALO + ((ks * 8 + wid) * 32 + lane) * 16);
        #pragma unroll
        for (int ni = 0; ni < 16; ni++) {
            uint2 vh = __ldg(&bh[(ks * 16 + ni) * 32 + lane]);
            uint2 vl = __ldg(&bl[(ks * 16 + ni) * 32 + lane]);
            u32 bhv[2] = {vh.x, vh.y};
            u32 blv[2] = {vl.x, vl.y};
            mma_bf16(c[ni], ah, bhv);   // Ah*Bh
            mma_bf16(c[ni], al, bhv);   // Al*Bh
            mma_bf16(c[ni], ah, blv);   // Ah*Bl
        }
    }
}

// ---------------------------------------------------------------------------
// gemm_pre: hpre = A @ W_pre + b_pre ; zeroes agg (fused).
// ---------------------------------------------------------------------------
__global__ void __launch_bounds__(256, 2)
gemm_pre(const float* __restrict__ A, const float* __restrict__ bias,
         const uint2* __restrict__ bh, const uint2* __restrict__ bl,
         float* __restrict__ out, float* __restrict__ zbuf, int nrows) {
    extern __shared__ char smem[];
    const int tid = threadIdx.x, wid = tid >> 5, lane = tid & 31;
    const int base = blockIdx.x * TILE_M;

    float* bias_s = (float*)(smem + SM_B1);
    if (tid < 128) bias_s[tid] = bias[tid];
    stage_A(smem, A, base, nrows, tid);
    __syncthreads();

    float c[16][4];
    #pragma unroll
    for (int ni = 0; ni < 16; ni++)
        #pragma unroll
        for (int r = 0; r < 4; r++) c[ni][r] = 0.f;

    mma_mainloop(smem, bh, bl, c, wid, lane);

    const int g = lane >> 2, t = lane & 3;
    const int row0 = base + wid * 16 + g, row1 = row0 + 8;
    const bool ok0 = row0 < nrows, ok1 = row1 < nrows;
    float2* out2 = (float2*)out;
    #pragma unroll
    for (int ni = 0; ni < 16; ni++) {
        int col = ni * 8 + t * 2;
        float2 b2 = *(const float2*)(bias_s + col);
        if (ok0) out2[(size_t)row0 * 64 + (col >> 1)] =
            make_float2(c[ni][0] + b2.x, c[ni][1] + b2.y);
        if (ok1) out2[(size_t)row1 * 64 + (col >> 1)] =
            make_float2(c[ni][2] + b2.x, c[ni][3] + b2.y);
    }
    // fused agg zeroing, coalesced
    float4* z4 = (float4*)zbuf;
    #pragma unroll 4
    for (int i = tid; i < 128 * 32; i += 256) {
        int row = i >> 5;
        if (base + row < nrows)
            z4[(size_t)(base + row) * 32 + (i & 31)] = make_float4(0.f, 0.f, 0.f, 0.f);
    }
}

// ---------------------------------------------------------------------------
// gemm_mlp: out = LayerNorm(resid + relu(relu(A@W1+b1)@W2+b2)) * gamma + beta
// Two fused GEMMs; intermediate converted in-lane back into A-frag smem.
// ---------------------------------------------------------------------------
__global__ void __launch_bounds__(256, 1)
gemm_mlp(const float* __restrict__ A,
         const float* __restrict__ b1v, const float* __restrict__ b2v,
         const uint2* __restrict__ b1h, const uint2* __restrict__ b1l,
         const uint2* __restrict__ b2h, const uint2* __restrict__ b2l,
         const float* __restrict__ resid,
         const float* __restrict__ gamma, const float* __restrict__ beta,
         float* __restrict__ out, int nrows) {
    extern __shared__ char smem[];
    const int tid = threadIdx.x, wid = tid >> 5, lane = tid & 31;
    const int base = blockIdx.x * TILE_M;

    float* b1_s = (float*)(smem + SM_B1);
    float* b2_s = (float*)(smem + SM_B2);
    float* gm_s = (float*)(smem + SM_GAMMA);
    float* bt_s = (float*)(smem + SM_BETA);
    if (tid < 128) {
        b1_s[tid] = b1v[tid];
        b2_s[tid] = b2v[tid];
        gm_s[tid] = gamma[tid];
        bt_s[tid] = beta[tid];
    }
    stage_A(smem, A, base, nrows, tid);
    __syncthreads();

    float c[16][4];
    #pragma unroll
    for (int ni = 0; ni < 16; ni++)
        #pragma unroll
        for (int r = 0; r < 4; r++) c[ni][r] = 0.f;

    // ---- GEMM 1: c = A @ W1 ----
    mma_mainloop(smem, b1h, b1l, c, wid, lane);

    // ---- Convert t1 = relu(c + b1) in-lane into A-frag smem slots ----
    // Lane g*4+t holds rows {g, g+8}, cols ni*8+2t, +2t+1 (= k-pair j=4ni+t).
    // Target frag: ks=ni>>1, mi=wid, lane=g*4+t (self), reg=(ni&1)*2+rowbit.
    // Each lane rewrites exactly the 16B it alone reads in the mainloop.
    const int g = lane >> 2, t = lane & 3;
    {
        #pragma unroll
        for (int ks = 0; ks < 8; ks++) {
            u32 vh[4], vl[4];
            #pragma unroll
            for (int half = 0; half < 2; half++) {   // ni = 2*ks + half
                int ni = 2 * ks + half;
                int col = ni * 8 + t * 2;
                float2 b2 = *(const float2*)(b1_s + col);
                float v00 = fmaxf(c[ni][0] + b2.x, 0.f);
                float v01 = fmaxf(c[ni][1] + b2.y, 0.f);
                float v10 = fmaxf(c[ni][2] + b2.x, 0.f);
                float v11 = fmaxf(c[ni][3] + b2.y, 0.f);
                __nv_bfloat16 h00, l00, h01, l01, h10, l10, h11, l11;
                split2(v00, h00, l00); split2(v01, h01, l01);
                split2(v10, h10, l10); split2(v11, h11, l11);
                vh[half * 2 + 0] = pack_bf16x2(h00, h01);  // row0 k-pair
                vh[half * 2 + 1] = pack_bf16x2(h10, h11);  // row1 k-pair
                vl[half * 2 + 0] = pack_bf16x2(l00, l01);
                vl[half * 2 + 1] = pack_bf16x2(l10, l11);
            }
            int off = ((ks * 8 + wid) * 32 + lane) * 16;
            *(uint4*)(smem + SM_AHI + off) = *(uint4*)vh;
            *(uint4*)(smem + SM_ALO + off) = *(uint4*)vl;
        }
    }
    // no __syncthreads needed: every lane reads only its own rewritten 16B

    #pragma unroll
    for (int ni = 0; ni < 16; ni++)
        #pragma unroll
        for (int r = 0; r < 4; r++) c[ni][r] = 0.f;

    // ---- GEMM 2: c = t1 @ W2 ----
    mma_mainloop(smem, b2h, b2l, c, wid, lane);

    // ---- Epilogue: v = resid + relu(c + b2); out = LN(v)*gamma + beta ----
    const int row0 = base + wid * 16 + g, row1 = row0 + 8;
    const bool ok0 = row0 < nrows, ok1 = row1 < nrows;
    const float2* R2 = (const float2*)resid;
    float s0 = 0.f, q0 = 0.f, s1 = 0.f, q1 = 0.f;
    #pragma unroll
    for (int ni = 0; ni < 16; ni++) {
        int col = ni * 8 + t * 2;
        float2 b2 = *(const float2*)(b2_s + col);
        float2 r0 = ok0 ? R2[(size_t)row0 * 64 + (col >> 1)] : make_float2(0.f, 0.f);
        float2 r1 = ok1 ? R2[(size_t)row1 * 64 + (col >> 1)] : make_float2(0.f, 0.f);
        float v00 = fmaxf(c[ni][0] + b2.x, 0.f) + r0.x;
        float v01 = fmaxf(c[ni][1] + b2.y, 0.f) + r0.y;
        float v10 = fmaxf(c[ni][2] + b2.x, 0.f) + r1.x;
        float v11 = fmaxf(c[ni][3] + b2.y, 0.f) + r1.y;
        c[ni][0] = v00; c[ni][1] = v01; c[ni][2] = v10; c[ni][3] = v11;
        s0 += v00 + v01; q0 += v00 * v00 + v01 * v01;
        s1 += v10 + v11; q1 += v10 * v10 + v11 * v11;
    }
    #pragma unroll
    for (int off = 1; off <= 2; off <<= 1) {
        s0 += __shfl_xor_sync(0xFFFFFFFFu, s0, off);
        q0 += __shfl_xor_sync(0xFFFFFFFFu, q0, off);
        s1 += __shfl_xor_sync(0xFFFFFFFFu, s1, off);
        q1 += __shfl_xor_sync(0xFFFFFFFFu, q1, off);
    }
    float mean0 = s0 * (1.0f / D_DIM);
    float mean1 = s1 * (1.0f / D_DIM);
    float rstd0 = rsqrtf(q0 * (1.0f / D_DIM) - mean0 * mean0 + LN_EPS);
    float rstd1 = rsqrtf(q1 * (1.0f / D_DIM) - mean1 * mean1 + LN_EPS);
    float2* out2 = (float2*)out;
    #pragma unroll
    for (int ni = 0; ni < 16; ni++) {
        int col = ni * 8 + t * 2;
        float2 g2 = *(const float2*)(gm_s + col);
        float2 t2 = *(const float2*)(bt_s + col);
        if (ok0) {
            float2 o;
            o.x = (c[ni][0] - mean0) * rstd0 * g2.x + t2.x;
            o.y = (c[ni][1] - mean0) * rstd0 * g2.y + t2.y;
            out2[(size_t)row0 * 64 + (col >> 1)] = o;
        }
        if (ok1) {
            float2 o;
            o.x = (c[ni][2] - mean1) * rstd1 * g2.x + t2.x;
            o.y = (c[ni][3] - mean1) * rstd1 * g2.y + t2.y;
            out2[(size_t)row1 * 64 + (col >> 1)] = o;
        }
    }
}

// ---------------------------------------------------------------------------
extern "C" void kernel_launch(void* const* d_in, const int* in_sizes, int n_in,
                              void* d_out, int out_size) {
    const float* h     = (const float*)d_in[0];
    const int*   src   = (const int*)  d_in[1];
    const int*   dst   = (const int*)  d_in[2];
    const float* W_pre = (const float*)d_in[3];
    const float* b_pre = (const float*)d_in[4];
    const float* W1    = (const float*)d_in[5];
    const float* b1    = (const float*)d_in[6];
    const float* W2    = (const float*)d_in[7];
    const float* b2    = (const float*)d_in[8];
    const float* gamma = (const float*)d_in[9];
    const float* beta  = (const float*)d_in[10];
    float* out = (float*)d_out;

    float *hpre, *agg;
    u32 *bfh, *bfl;
    cudaGetSymbolAddress((void**)&hpre, g_hpre);
    cudaGetSymbolAddress((void**)&agg,  g_agg);
    cudaGetSymbolAddress((void**)&bfh,  g_bf_hi);
    cudaGetSymbolAddress((void**)&bfl,  g_bf_lo);
    const uint2* wph = (const uint2*)(bfh);            // W_pre hi
    const uint2* wpl = (const uint2*)(bfl);
    const uint2* w1h = (const uint2*)(bfh + 8192);     // W1
    const uint2* w1l = (const uint2*)(bfl + 8192);
    const uint2* w2h = (const uint2*)(bfh + 16384);    // W2
    const uint2* w2l = (const uint2*)(bfl + 16384);

    cudaFuncSetAttribute(gemm_pre, cudaFuncAttributeMaxDynamicSharedMemorySize, SMEM_TOTAL);
    cudaFuncSetAttribute(gemm_mlp, cudaFuncAttributeMaxDynamicSharedMemorySize, SMEM_TOTAL);

    const int blocks = (N_NODES + TILE_M - 1) / TILE_M;  // 391

    // 0. convert weights into fragment layout (hi/lo)
    wprep_kernel<<<24, 256>>>(W_pre, W1, W2);
    // 1. hpre = h @ W_pre + b_pre   (also zeroes agg, fused)
    gemm_pre<<<blocks, 256, SMEM_TOTAL>>>(h, b_pre, wph, wpl, hpre, agg, N_NODES);
    // 2. agg[dst] += hpre[src]
    {
        long long threads = (long long)N_EDGES * 32;
        int nb = (int)((threads + 255) / 256);
        scatter_kernel<<<nb, 256>>>(hpre, src, dst, agg);
    }
    // 3. out = LN(hpre + relu(relu(agg@W1+b1)@W2+b2))
    gemm_mlp<<<blocks, 256, SMEM_TOTAL>>>(agg, b1, b2, w1h, w1l, w2h, w2l,
                                          hpre, gamma, beta, out, N_NODES);
    (void)in_sizes; (void)n_in; (void)out_size;
}

// round 8
// speedup vs baseline: 1.5100x; 1.0244x over previous
#include <cuda_runtime.h>
#include <cuda_bf16.h>
#include <math.h>
#include <stdint.h>

#define D_DIM 128
#define N_NODES 50000
#define N_EDGES 600000
#define LN_EPS 1e-5f
#define TILE_M 128
#define NTHREADS 512

typedef unsigned int u32;

// Scratch (allocation-free rule: __device__ globals)
__device__ float g_hpre[N_NODES * D_DIM];
__device__ float g_agg [N_NODES * D_DIM];
// Precomputed W fragments: [w][((ks*16+ni)*32+lane)*2 + reg], w=0:W_pre 1:W1 2:W2
__device__ u32 g_bf_hi[3][8192];
__device__ u32 g_bf_lo[3][8192];

// ---------------- smem layout (bytes) ----------------
#define SM_B1     0
#define SM_B2     512
#define SM_GAMMA  1024
#define SM_BETA   1536
#define SM_RED    2048         // 128 rows x 2 halves x float2(s,q) = 2KB
#define SM_AHI    4096         // A frags [ks8][mi8][lane32] x 16B = 32KB
#define SM_ALO    (SM_AHI + 32768)
#define SMEM_TOTAL (SM_ALO + 32768)   // 69632

__device__ __forceinline__ u32 pack_bf16x2(__nv_bfloat16 lo, __nv_bfloat16 hi) {
    __nv_bfloat162 v; v.x = lo; v.y = hi;
    return *(u32*)&v;
}
__device__ __forceinline__ void split2(float a, __nv_bfloat16& hi, __nv_bfloat16& lo) {
    hi = __float2bfloat16_rn(a);
    lo = __float2bfloat16_rn(a - __bfloat162float(hi));
}
__device__ __forceinline__ void mma_bf16(float* c, const u32* a, const u32* b) {
    asm volatile(
        "mma.sync.aligned.m16n8k16.row.col.f32.bf16.bf16.f32 "
        "{%0,%1,%2,%3}, {%4,%5,%6,%7}, {%8,%9}, {%0,%1,%2,%3};"
        : "+f"(c[0]), "+f"(c[1]), "+f"(c[2]), "+f"(c[3])
        : "r"(a[0]), "r"(a[1]), "r"(a[2]), "r"(a[3]), "r"(b[0]), "r"(b[1]));
}

// ---------------------------------------------------------------------------
// W prep: convert 3 weight matrices into global hi/lo B-fragment arrays.
// ---------------------------------------------------------------------------
__global__ void wprep_kernel(const float* __restrict__ W0,
                             const float* __restrict__ W1,
                             const float* __restrict__ W2) {
    const float* Ws[3] = {W0, W1, W2};
    int w = blockIdx.x >> 3, part = blockIdx.x & 7;
    const float* W = Ws[w];
    u32* bh = g_bf_hi[w];
    u32* bl = g_bf_lo[w];
    for (int i = part * 1024 + threadIdx.x; i < (part + 1) * 1024; i += 256) {
        int j = i >> 7, n = i & 127;
        float w0 = W[(size_t)(2 * j)     * 128 + n];
        float w1 = W[(size_t)(2 * j + 1) * 128 + n];
        __nv_bfloat16 h0, l0, h1, l1;
        split2(w0, h0, l0);
        split2(w1, h1, l1);
        int ni = n >> 3, ks = j >> 3;
        int ln = ((n & 7) << 2) | (j & 3);
        int reg = (j >> 2) & 1;
        int idx = ((ks * 16 + ni) * 32 + ln) * 2 + reg;
        bh[idx] = pack_bf16x2(h0, h1);
        bl[idx] = pack_bf16x2(l0, l1);
    }
}

// ---------------------------------------------------------------------------
// Edge scatter (proven): warp per edge, red.global.add.v4
// ---------------------------------------------------------------------------
__global__ void scatter_kernel(const float* __restrict__ hpre,
                               const int* __restrict__ src,
                               const int* __restrict__ dst,
                               float* __restrict__ agg) {
    int gid  = blockIdx.x * blockDim.x + threadIdx.x;
    int e    = gid >> 5;
    int lane = gid & 31;
    if (e >= N_EDGES) return;
    int s = src[e];
    int d = dst[e];
    float4 v = ((const float4*)(hpre + (size_t)s * D_DIM))[lane];
    float* o = agg + (size_t)d * D_DIM + lane * 4;
    asm volatile("red.global.add.v4.f32 [%0], {%1, %2, %3, %4};"
                 :: "l"(o), "f"(v.x), "f"(v.y), "f"(v.z), "f"(v.w)
                 : "memory");
}

// ---------------------------------------------------------------------------
// Shared building blocks (512-thread versions)
// ---------------------------------------------------------------------------
__device__ __forceinline__ void stage_A(char* smem, const float* __restrict__ A,
                                        int base, int nrows, int tid) {
    const float2* A2 = (const float2*)A;
    #pragma unroll 4
    for (int i = tid; i < 128 * 64; i += NTHREADS) {
        int row = i >> 6, j = i & 63;
        float2 a = (base + row < nrows) ? A2[(size_t)(base + row) * 64 + j]
                                        : make_float2(0.f, 0.f);
        __nv_bfloat16 hx, lx, hy, ly;
        split2(a.x, hx, lx);
        split2(a.y, hy, ly);
        int mi = row >> 4, ks = j >> 3;
        int ln = ((row & 7) << 2) | (j & 3);
        int reg = (((j >> 2) & 1) << 1) | ((row >> 3) & 1);
        int off = ((ks * 8 + mi) * 32 + ln) * 16 + reg * 4;
        *(u32*)(smem + SM_AHI + off) = pack_bf16x2(hx, hy);
        *(u32*)(smem + SM_ALO + off) = pack_bf16x2(lx, ly);
    }
}

// Half-n mainloop: warp (wid_m, wid_n) computes 16 rows x 64 cols.
// c[q][4], q -> ni = wid_n*8 + q.
__device__ __forceinline__ void mma_mainloop(const char* smem,
                                             const uint2* __restrict__ bh,
                                             const uint2* __restrict__ bl,
                                             float c[8][4],
                                             int wid_m, int wid_n, int lane) {
    #pragma unroll
    for (int ks = 0; ks < 8; ks++) {
        u32 ah[4], al[4];
        *(uint4*)ah = *(const uint4*)(smem + SM_AHI + ((ks * 8 + wid_m) * 32 + lane) * 16);
        *(uint4*)al = *(const uint4*)(smem + SM_ALO + ((ks * 8 + wid_m) * 32 + lane) * 16);
        #pragma unroll
        for (int q = 0; q < 8; q++) {
            int ni = wid_n * 8 + q;
            uint2 vh = __ldg(&bh[(ks * 16 + ni) * 32 + lane]);
            uint2 vl = __ldg(&bl[(ks * 16 + ni) * 32 + lane]);
            u32 bhv[2] = {vh.x, vh.y};
            u32 blv[2] = {vl.x, vl.y};
            mma_bf16(c[q], ah, bhv);   // Ah*Bh
            mma_bf16(c[q], al, bhv);   // Al*Bh
            mma_bf16(c[q], ah, blv);   // Ah*Bl
        }
    }
}

// ---------------------------------------------------------------------------
// gemm_pre: hpre = A @ W_pre + b_pre ; zeroes agg (fused).
// ---------------------------------------------------------------------------
__global__ void __launch_bounds__(NTHREADS, 1)
gemm_pre(const float* __restrict__ A, const float* __restrict__ bias,
         const uint2* __restrict__ bh, const uint2* __restrict__ bl,
         float* __restrict__ out, float* __restrict__ zbuf, int nrows) {
    extern __shared__ char smem[];
    const int tid = threadIdx.x, wid = tid >> 5, lane = tid & 31;
    const int wid_m = wid >> 1, wid_n = wid & 1;
    const int base = blockIdx.x * TILE_M;

    float* bias_s = (float*)(smem + SM_B1);
    if (tid < 128) bias_s[tid] = bias[tid];
    stage_A(smem, A, base, nrows, tid);
    __syncthreads();

    float c[8][4];
    #pragma unroll
    for (int q = 0; q < 8; q++)
        #pragma unroll
        for (int r = 0; r < 4; r++) c[q][r] = 0.f;

    mma_mainloop(smem, bh, bl, c, wid_m, wid_n, lane);

    const int g = lane >> 2, t = lane & 3;
    const int row0 = base + wid_m * 16 + g, row1 = row0 + 8;
    const bool ok0 = row0 < nrows, ok1 = row1 < nrows;
    float2* out2 = (float2*)out;
    #pragma unroll
    for (int q = 0; q < 8; q++) {
        int col = (wid_n * 8 + q) * 8 + t * 2;
        float2 b2 = *(const float2*)(bias_s + col);
        if (ok0) out2[(size_t)row0 * 64 + (col >> 1)] =
            make_float2(c[q][0] + b2.x, c[q][1] + b2.y);
        if (ok1) out2[(size_t)row1 * 64 + (col >> 1)] =
            make_float2(c[q][2] + b2.x, c[q][3] + b2.y);
    }
    // fused agg zeroing, coalesced
    float4* z4 = (float4*)zbuf;
    #pragma unroll 2
    for (int i = tid; i < 128 * 32; i += NTHREADS) {
        int row = i >> 5;
        if (base + row < nrows)
            z4[(size_t)(base + row) * 32 + (i & 31)] = make_float4(0.f, 0.f, 0.f, 0.f);
    }
}

// ---------------------------------------------------------------------------
// gemm_mlp: out = LayerNorm(resid + relu(relu(A@W1+b1)@W2+b2)) * gamma + beta
// ---------------------------------------------------------------------------
__global__ void __launch_bounds__(NTHREADS, 1)
gemm_mlp(const float* __restrict__ A,
         const float* __restrict__ b1v, const float* __restrict__ b2v,
         const uint2* __restrict__ b1h, const uint2* __restrict__ b1l,
         const uint2* __restrict__ b2h, const uint2* __restrict__ b2l,
         const float* __restrict__ resid,
         const float* __restrict__ gamma, const float* __restrict__ beta,
         float* __restrict__ out, int nrows) {
    extern __shared__ char smem[];
    const int tid = threadIdx.x, wid = tid >> 5, lane = tid & 31;
    const int wid_m = wid >> 1, wid_n = wid & 1;
    const int base = blockIdx.x * TILE_M;

    float* b1_s = (float*)(smem + SM_B1);
    float* b2_s = (float*)(smem + SM_B2);
    float* gm_s = (float*)(smem + SM_GAMMA);
    float* bt_s = (float*)(smem + SM_BETA);
    float2* red = (float2*)(smem + SM_RED);   // [row][half]
    if (tid < 128) {
        b1_s[tid] = b1v[tid];
        b2_s[tid] = b2v[tid];
        gm_s[tid] = gamma[tid];
        bt_s[tid] = beta[tid];
    }
    stage_A(smem, A, base, nrows, tid);
    __syncthreads();

    float c[8][4];
    #pragma unroll
    for (int q = 0; q < 8; q++)
        #pragma unroll
        for (int r = 0; r < 4; r++) c[q][r] = 0.f;

    // ---- GEMM 1: c = A @ W1 (this warp's n-half) ----
    mma_mainloop(smem, b1h, b1l, c, wid_m, wid_n, lane);

    __syncthreads();   // all warps done reading A-frags before overwrite

    // ---- Convert t1 = relu(c + b1) into A-frag smem ----
    // Warp (wid_m, wid_n) owns ni = wid_n*8 + q -> writes ks = wid_n*4 + q2
    // (q = 2*q2, 2*q2+1), full uint4 per ks at mi=wid_m, lane=self.
    const int g = lane >> 2, t = lane & 3;
    {
        #pragma unroll
        for (int q2 = 0; q2 < 4; q2++) {
            int ks = wid_n * 4 + q2;
            u32 vh[4], vl[4];
            #pragma unroll
            for (int half = 0; half < 2; half++) {
                int q = 2 * q2 + half;
                int col = (wid_n * 8 + q) * 8 + t * 2;
                float2 b2 = *(const float2*)(b1_s + col);
                float v00 = fmaxf(c[q][0] + b2.x, 0.f);
                float v01 = fmaxf(c[q][1] + b2.y, 0.f);
                float v10 = fmaxf(c[q][2] + b2.x, 0.f);
                float v11 = fmaxf(c[q][3] + b2.y, 0.f);
                __nv_bfloat16 h00, l00, h01, l01, h10, l10, h11, l11;
                split2(v00, h00, l00); split2(v01, h01, l01);
                split2(v10, h10, l10); split2(v11, h11, l11);
                vh[half * 2 + 0] = pack_bf16x2(h00, h01);
                vh[half * 2 + 1] = pack_bf16x2(h10, h11);
                vl[half * 2 + 0] = pack_bf16x2(l00, l01);
                vl[half * 2 + 1] = pack_bf16x2(l10, l11);
            }
            int off = ((ks * 8 + wid_m) * 32 + lane) * 16;
            *(uint4*)(smem + SM_AHI + off) = *(uint4*)vh;
            *(uint4*)(smem + SM_ALO + off) = *(uint4*)vl;
        }
    }
    __syncthreads();   // partner warp's ks-half must be visible

    #pragma unroll
    for (int q = 0; q < 8; q++)
        #pragma unroll
        for (int r = 0; r < 4; r++) c[q][r] = 0.f;

    // ---- GEMM 2: c = t1 @ W2 ----
    mma_mainloop(smem, b2h, b2l, c, wid_m, wid_n, lane);

    // ---- Epilogue: v = resid + relu(c + b2); out = LN(v)*gamma + beta ----
    const int row0 = base + wid_m * 16 + g, row1 = row0 + 8;
    const int lr0 = wid_m * 16 + g, lr1 = lr0 + 8;
    const bool ok0 = row0 < nrows, ok1 = row1 < nrows;
    const float2* R2 = (const float2*)resid;
    float s0 = 0.f, q0 = 0.f, s1 = 0.f, q1 = 0.f;
    #pragma unroll
    for (int q = 0; q < 8; q++) {
        int col = (wid_n * 8 + q) * 8 + t * 2;
        float2 b2 = *(const float2*)(b2_s + col);
        float2 r0 = ok0 ? R2[(size_t)row0 * 64 + (col >> 1)] : make_float2(0.f, 0.f);
        float2 r1 = ok1 ? R2[(size_t)row1 * 64 + (col >> 1)] : make_float2(0.f, 0.f);
        float v00 = fmaxf(c[q][0] + b2.x, 0.f) + r0.x;
        float v01 = fmaxf(c[q][1] + b2.y, 0.f) + r0.y;
        float v10 = fmaxf(c[q][2] + b2.x, 0.f) + r1.x;
        float v11 = fmaxf(c[q][3] + b2.y, 0.f) + r1.y;
        c[q][0] = v00; c[q][1] = v01; c[q][2] = v10; c[q][3] = v11;
        s0 += v00 + v01; q0 += v00 * v00 + v01 * v01;
        s1 += v10 + v11; q1 += v10 * v10 + v11 * v11;
    }
    // quad reduce (this warp's 64-col partial)
    #pragma unroll
    for (int off = 1; off <= 2; off <<= 1) {
        s0 += __shfl_xor_sync(0xFFFFFFFFu, s0, off);
        q0 += __shfl_xor_sync(0xFFFFFFFFu, q0, off);
        s1 += __shfl_xor_sync(0xFFFFFFFFu, s1, off);
        q1 += __shfl_xor_sync(0xFFFFFFFFu, q1, off);
    }
    if (t == 0) {
        red[lr0 * 2 + wid_n] = make_float2(s0, q0);
        red[lr1 * 2 + wid_n] = make_float2(s1, q1);
    }
    __syncthreads();
    {
        float2 a0 = red[lr0 * 2 + 0], a1 = red[lr0 * 2 + 1];
        float2 c0 = red[lr1 * 2 + 0], c1 = red[lr1 * 2 + 1];
        s0 = a0.x + a1.x; q0 = a0.y + a1.y;
        s1 = c0.x + c1.x; q1 = c0.y + c1.y;
    }
    float mean0 = s0 * (1.0f / D_DIM);
    float mean1 = s1 * (1.0f / D_DIM);
    float rstd0 = rsqrtf(q0 * (1.0f / D_DIM) - mean0 * mean0 + LN_EPS);
    float rstd1 = rsqrtf(q1 * (1.0f / D_DIM) - mean1 * mean1 + LN_EPS);
    float2* out2 = (float2*)out;
    #pragma unroll
    for (int q = 0; q < 8; q++) {
        int col = (wid_n * 8 + q) * 8 + t * 2;
        float2 g2 = *(const float2*)(gm_s + col);
        float2 t2 = *(const float2*)(bt_s + col);
        if (ok0) {
            float2 o;
            o.x = (c[q][0] - mean0) * rstd0 * g2.x + t2.x;
            o.y = (c[q][1] - mean0) * rstd0 * g2.y + t2.y;
            out2[(size_t)row0 * 64 + (col >> 1)] = o;
        }
        if (ok1) {
            float2 o;
            o.x = (c[q][2] - mean1) * rstd1 * g2.x + t2.x;
            o.y = (c[q][3] - mean1) * rstd1 * g2.y + t2.y;
            out2[(size_t)row1 * 64 + (col >> 1)] = o;
        }
    }
}

// ---------------------------------------------------------------------------
extern "C" void kernel_launch(void* const* d_in, const int* in_sizes, int n_in,
                              void* d_out, int out_size) {
    const float* h     = (const float*)d_in[0];
    const int*   src   = (const int*)  d_in[1];
    const int*   dst   = (const int*)  d_in[2];
    const float* W_pre = (const float*)d_in[3];
    const float* b_pre = (const float*)d_in[4];
    const float* W1    = (const float*)d_in[5];
    const float* b1    = (const float*)d_in[6];
    const float* W2    = (const float*)d_in[7];
    const float* b2    = (const float*)d_in[8];
    const float* gamma = (const float*)d_in[9];
    const float* beta  = (const float*)d_in[10];
    float* out = (float*)d_out;

    float *hpre, *agg;
    u32 *bfh, *bfl;
    cudaGetSymbolAddress((void**)&hpre, g_hpre);
    cudaGetSymbolAddress((void**)&agg,  g_agg);
    cudaGetSymbolAddress((void**)&bfh,  g_bf_hi);
    cudaGetSymbolAddress((void**)&bfl,  g_bf_lo);
    const uint2* wph = (const uint2*)(bfh);
    const uint2* wpl = (const uint2*)(bfl);
    const uint2* w1h = (const uint2*)(bfh + 8192);
    const uint2* w1l = (const uint2*)(bfl + 8192);
    const uint2* w2h = (const uint2*)(bfh + 16384);
    const uint2* w2l = (const uint2*)(bfl + 16384);

    cudaFuncSetAttribute(gemm_pre, cudaFuncAttributeMaxDynamicSharedMemorySize, SMEM_TOTAL);
    cudaFuncSetAttribute(gemm_mlp, cudaFuncAttributeMaxDynamicSharedMemorySize, SMEM_TOTAL);

    const int blocks = (N_NODES + TILE_M - 1) / TILE_M;  // 391

    // 0. convert weights into fragment layout (hi/lo)
    wprep_kernel<<<24, 256>>>(W_pre, W1, W2);
    // 1. hpre = h @ W_pre + b_pre   (also zeroes agg, fused)
    gemm_pre<<<blocks, NTHREADS, SMEM_TOTAL>>>(h, b_pre, wph, wpl, hpre, agg, N_NODES);
    // 2. agg[dst] += hpre[src]
    {
        long long threads = (long long)N_EDGES * 32;
        int nb = (int)((threads + 255) / 256);
        scatter_kernel<<<nb, 256>>>(hpre, src, dst, agg);
    }
    // 3. out = LN(hpre + relu(relu(agg@W1+b1)@W2+b2))
    gemm_mlp<<<blocks, NTHREADS, SMEM_TOTAL>>>(agg, b1, b2, w1h, w1l, w2h, w2l,
                                               hpre, gamma, beta, out, N_NODES);
    (void)in_sizes; (void)n_in; (void)out_size;
}

// round 9
// speedup vs baseline: 1.8799x; 1.2449x over previous
#include <cuda_runtime.h>
#include <cuda_bf16.h>
#include <math.h>
#include <stdint.h>

#define D_DIM 128
#define N_NODES 50000
#define N_EDGES 600000
#define LN_EPS 1e-5f
#define TILE_M 64
#define NT 256

typedef unsigned int u32;

// Scratch (allocation-free rule: __device__ globals)
__device__ float g_hpre[N_NODES * D_DIM];
__device__ float g_agg [N_NODES * D_DIM];
// Packed W fragments: [w][(ks*16+ni)*32+lane] = {hi0,hi1,lo0,lo1}
__device__ uint4 g_bfrag[3][4096];
// CSR build
__device__ int g_cnt[N_NODES];
__device__ int g_cur[N_NODES];
__device__ int g_off[N_NODES + 1];
__device__ int g_bsum[196];
__device__ int g_csr[N_EDGES];

// ---------------- smem layout (bytes) ----------------
#define SM_B1     0
#define SM_B2     512
#define SM_GAMMA  1024
#define SM_BETA   1536
#define SM_RED    2048          // 64 rows x 2 halves x float2 = 1KB
#define SM_AHI    4096          // A frags [ks8][mi4][lane32] x 16B = 16KB
#define SM_ALO    (SM_AHI + 16384)
#define SMEM_TOTAL (SM_ALO + 16384)   // 36864

__device__ __forceinline__ u32 pack_bf16x2(__nv_bfloat16 lo, __nv_bfloat16 hi) {
    __nv_bfloat162 v; v.x = lo; v.y = hi;
    return *(u32*)&v;
}
__device__ __forceinline__ void split2(float a, __nv_bfloat16& hi, __nv_bfloat16& lo) {
    hi = __float2bfloat16_rn(a);
    lo = __float2bfloat16_rn(a - __bfloat162float(hi));
}
__device__ __forceinline__ void mma_bf16(float* c, const u32* a, const u32* b) {
    asm volatile(
        "mma.sync.aligned.m16n8k16.row.col.f32.bf16.bf16.f32 "
        "{%0,%1,%2,%3}, {%4,%5,%6,%7}, {%8,%9}, {%0,%1,%2,%3};"
        : "+f"(c[0]), "+f"(c[1]), "+f"(c[2]), "+f"(c[3])
        : "r"(a[0]), "r"(a[1]), "r"(a[2]), "r"(a[3]), "r"(b[0]), "r"(b[1]));
}

// ---------------------------------------------------------------------------
// W prep: 3 weight matrices -> packed hi/lo B-fragment arrays.
// ---------------------------------------------------------------------------
__global__ void wprep_kernel(const float* __restrict__ W0,
                             const float* __restrict__ W1,
                             const float* __restrict__ W2) {
    const float* Ws[3] = {W0, W1, W2};
    int w = blockIdx.x >> 3, part = blockIdx.x & 7;
    const float* W = Ws[w];
    uint4* bf = g_bfrag[w];
    for (int i = part * 1024 + threadIdx.x; i < (part + 1) * 1024; i += 256) {
        int j = i >> 7, n = i & 127;
        float w0 = W[(size_t)(2 * j)     * 128 + n];
        float w1 = W[(size_t)(2 * j + 1) * 128 + n];
        __nv_bfloat16 h0, l0, h1, l1;
        split2(w0, h0, l0);
        split2(w1, h1, l1);
        int ni = n >> 3, ks = j >> 3;
        int ln = ((n & 7) << 2) | (j & 3);
        int reg = (j >> 2) & 1;
        // two (j,n) pairs share a uint4 (reg 0/1) -> write u32 lanes separately
        u32* slot = (u32*)&bf[(ks * 16 + ni) * 32 + ln];
        slot[reg]     = pack_bf16x2(h0, h1);
        slot[2 + reg] = pack_bf16x2(l0, l1);
    }
}

// ---------------------------------------------------------------------------
// CSR build kernels
// ---------------------------------------------------------------------------
__global__ void zero_cnt_kernel() {
    int i = blockIdx.x * blockDim.x + threadIdx.x;
    if (i < N_NODES) g_cnt[i] = 0;
}
__global__ void hist_kernel(const int* __restrict__ dst) {
    int e = blockIdx.x * blockDim.x + threadIdx.x;
    if (e < N_EDGES) atomicAdd(&g_cnt[dst[e]], 1);
}
__global__ void bsum_kernel() {
    __shared__ int s[256];
    int n = blockIdx.x * 256 + threadIdx.x;
    s[threadIdx.x] = (n < N_NODES) ? g_cnt[n] : 0;
    __syncthreads();
    for (int w = 128; w > 0; w >>= 1) {
        if (threadIdx.x < w) s[threadIdx.x] += s[threadIdx.x + w];
        __syncthreads();
    }
    if (threadIdx.x == 0) g_bsum[blockIdx.x] = s[0];
}
__global__ void offs_kernel() {
    __shared__ int sp[256];
    __shared__ int ss[256];
    int b = blockIdx.x, t = threadIdx.x;
    int n = b * 256 + t;
    // block prefix = sum of bsum[0..b)
    sp[t] = (t < b) ? g_bsum[t] : 0;
    __syncthreads();
    for (int w = 128; w > 0; w >>= 1) {
        if (t < w) sp[t] += sp[t + w];
        __syncthreads();
    }
    int bpref = sp[0];
    // inclusive scan of counts within block (Hillis-Steele)
    int cnt = (n < N_NODES) ? g_cnt[n] : 0;
    int x = cnt;
    ss[t] = x;
    __syncthreads();
    #pragma unroll
    for (int w = 1; w < 256; w <<= 1) {
        int y = (t >= w) ? ss[t - w] : 0;
        __syncthreads();
        x += y;
        ss[t] = x;
        __syncthreads();
    }
    int off = bpref + x - cnt;   // exclusive
    if (n < N_NODES) { g_off[n] = off; g_cur[n] = off; }
    if (b == 195 && t == 255) g_off[N_NODES] = N_EDGES;
}
__global__ void fill_kernel(const int* __restrict__ src,
                            const int* __restrict__ dst) {
    int e = blockIdx.x * blockDim.x + threadIdx.x;
    if (e < N_EDGES) {
        int p = atomicAdd(&g_cur[dst[e]], 1);
        g_csr[p] = src[e];
    }
}
// Gather-sum: one warp per node, no atomics, writes agg once.
__global__ void gather_kernel(const float* __restrict__ hpre,
                              float* __restrict__ agg) {
    int gid  = blockIdx.x * blockDim.x + threadIdx.x;
    int node = gid >> 5;
    int lane = gid & 31;
    if (node >= N_NODES) return;
    int e0 = g_off[node], e1 = g_off[node + 1];
    float4 acc = make_float4(0.f, 0.f, 0.f, 0.f);
    const float4* h4 = (const float4*)hpre;
    for (int e = e0; e < e1; e++) {
        int s = g_csr[e];
        float4 v = __ldg(&h4[(size_t)s * 32 + lane]);
        acc.x += v.x; acc.y += v.y; acc.z += v.z; acc.w += v.w;
    }
    ((float4*)agg)[(size_t)node * 32 + lane] = acc;
}

// ---------------------------------------------------------------------------
// GEMM building blocks: TILE_M=64, 256 threads, 8 warps = (m 0..3, n 0..1)
// ---------------------------------------------------------------------------
__device__ __forceinline__ void stage_A(char* smem, const float* __restrict__ A,
                                        int base, int nrows, int tid) {
    const float2* A2 = (const float2*)A;
    #pragma unroll 4
    for (int i = tid; i < TILE_M * 64; i += NT) {
        int row = i >> 6, j = i & 63;
        float2 a = (base + row < nrows) ? A2[(size_t)(base + row) * 64 + j]
                                        : make_float2(0.f, 0.f);
        __nv_bfloat16 hx, lx, hy, ly;
        split2(a.x, hx, lx);
        split2(a.y, hy, ly);
        int mi = row >> 4, ks = j >> 3;
        int ln = ((row & 7) << 2) | (j & 3);
        int reg = (((j >> 2) & 1) << 1) | ((row >> 3) & 1);
        int off = ((ks * 4 + mi) * 32 + ln) * 16 + reg * 4;
        *(u32*)(smem + SM_AHI + off) = pack_bf16x2(hx, hy);
        *(u32*)(smem + SM_ALO + off) = pack_bf16x2(lx, ly);
    }
}

__device__ __forceinline__ void mma_mainloop(const char* smem,
                                             const uint4* __restrict__ bf,
                                             float c[8][4],
                                             int wid_m, int wid_n, int lane) {
    #pragma unroll
    for (int ks = 0; ks < 8; ks++) {
        u32 ah[4], al[4];
        *(uint4*)ah = *(const uint4*)(smem + SM_AHI + ((ks * 4 + wid_m) * 32 + lane) * 16);
        *(uint4*)al = *(const uint4*)(smem + SM_ALO + ((ks * 4 + wid_m) * 32 + lane) * 16);
        #pragma unroll
        for (int q = 0; q < 8; q++) {
            uint4 v = __ldg(&bf[(ks * 16 + wid_n * 8 + q) * 32 + lane]);
            u32 bh[2] = {v.x, v.y};
            u32 bl[2] = {v.z, v.w};
            mma_bf16(c[q], ah, bh);   // Ah*Bh
            mma_bf16(c[q], al, bh);   // Al*Bh
            mma_bf16(c[q], ah, bl);   // Ah*Bl
        }
    }
}

// ---------------------------------------------------------------------------
// gemm_pre: hpre = A @ W_pre + b_pre
// ---------------------------------------------------------------------------
__global__ void __launch_bounds__(NT, 2)
gemm_pre(const float* __restrict__ A, const float* __restrict__ bias,
         const uint4* __restrict__ bf, float* __restrict__ out, int nrows) {
    extern __shared__ char smem[];
    const int tid = threadIdx.x, wid = tid >> 5, lane = tid & 31;
    const int wid_m = wid >> 1, wid_n = wid & 1;
    const int base = blockIdx.x * TILE_M;

    float* bias_s = (float*)(smem + SM_B1);
    if (tid < 128) bias_s[tid] = bias[tid];
    stage_A(smem, A, base, nrows, tid);
    __syncthreads();

    float c[8][4];
    #pragma unroll
    for (int q = 0; q < 8; q++)
        #pragma unroll
        for (int r = 0; r < 4; r++) c[q][r] = 0.f;

    mma_mainloop(smem, bf, c, wid_m, wid_n, lane);

    const int g = lane >> 2, t = lane & 3;
    const int row0 = base + wid_m * 16 + g, row1 = row0 + 8;
    const bool ok0 = row0 < nrows, ok1 = row1 < nrows;
    float2* out2 = (float2*)out;
    #pragma unroll
    for (int q = 0; q < 8; q++) {
        int col = (wid_n * 8 + q) * 8 + t * 2;
        float2 b2 = *(const float2*)(bias_s + col);
        if (ok0) out2[(size_t)row0 * 64 + (col >> 1)] =
            make_float2(c[q][0] + b2.x, c[q][1] + b2.y);
        if (ok1) out2[(size_t)row1 * 64 + (col >> 1)] =
            make_float2(c[q][2] + b2.x, c[q][3] + b2.y);
    }
}

// ---------------------------------------------------------------------------
// gemm_mlp: out = LayerNorm(resid + relu(relu(A@W1+b1)@W2+b2)) * gamma + beta
// ---------------------------------------------------------------------------
__global__ void __launch_bounds__(NT, 2)
gemm_mlp(const float* __restrict__ A,
         const float* __restrict__ b1v, const float* __restrict__ b2v,
         const uint4* __restrict__ bf1, const uint4* __restrict__ bf2,
         const float* __restrict__ resid,
         const float* __restrict__ gamma, const float* __restrict__ beta,
         float* __restrict__ out, int nrows) {
    extern __shared__ char smem[];
    const int tid = threadIdx.x, wid = tid >> 5, lane = tid & 31;
    const int wid_m = wid >> 1, wid_n = wid & 1;
    const int base = blockIdx.x * TILE_M;

    float* b1_s = (float*)(smem + SM_B1);
    float* b2_s = (float*)(smem + SM_B2);
    float* gm_s = (float*)(smem + SM_GAMMA);
    float* bt_s = (float*)(smem + SM_BETA);
    float2* red = (float2*)(smem + SM_RED);
    if (tid < 128) {
        b1_s[tid] = b1v[tid];
        b2_s[tid] = b2v[tid];
        gm_s[tid] = gamma[tid];
        bt_s[tid] = beta[tid];
    }
    stage_A(smem, A, base, nrows, tid);
    __syncthreads();

    float c[8][4];
    #pragma unroll
    for (int q = 0; q < 8; q++)
        #pragma unroll
        for (int r = 0; r < 4; r++) c[q][r] = 0.f;

    // ---- GEMM 1: c = A @ W1 ----
    mma_mainloop(smem, bf1, c, wid_m, wid_n, lane);

    __syncthreads();   // all warps done reading A-frags before overwrite

    // ---- Convert t1 = relu(c + b1) into A-frag smem (in-lane mapping) ----
    const int g = lane >> 2, t = lane & 3;
    {
        #pragma unroll
        for (int q2 = 0; q2 < 4; q2++) {
            int ks = wid_n * 4 + q2;
            u32 vh[4], vl[4];
            #pragma unroll
            for (int half = 0; half < 2; half++) {
                int q = 2 * q2 + half;
                int col = (wid_n * 8 + q) * 8 + t * 2;
                float2 b2 = *(const float2*)(b1_s + col);
                float v00 = fmaxf(c[q][0] + b2.x, 0.f);
                float v01 = fmaxf(c[q][1] + b2.y, 0.f);
                float v10 = fmaxf(c[q][2] + b2.x, 0.f);
                float v11 = fmaxf(c[q][3] + b2.y, 0.f);
                __nv_bfloat16 h00, l00, h01, l01, h10, l10, h11, l11;
                split2(v00, h00, l00); split2(v01, h01, l01);
                split2(v10, h10, l10); split2(v11, h11, l11);
                vh[half * 2 + 0] = pack_bf16x2(h00, h01);
                vh[half * 2 + 1] = pack_bf16x2(h10, h11);
                vl[half * 2 + 0] = pack_bf16x2(l00, l01);
                vl[half * 2 + 1] = pack_bf16x2(l10, l11);
            }
            int off = ((ks * 4 + wid_m) * 32 + lane) * 16;
            *(uint4*)(smem + SM_AHI + off) = *(uint4*)vh;
            *(uint4*)(smem + SM_ALO + off) = *(uint4*)vl;
        }
    }
    __syncthreads();

    #pragma unroll
    for (int q = 0; q < 8; q++)
        #pragma unroll
        for (int r = 0; r < 4; r++) c[q][r] = 0.f;

    // ---- GEMM 2: c = t1 @ W2 ----
    mma_mainloop(smem, bf2, c, wid_m, wid_n, lane);

    // ---- Epilogue: v = resid + relu(c + b2); out = LN(v)*gamma + beta ----
    const int row0 = base + wid_m * 16 + g, row1 = row0 + 8;
    const int lr0 = wid_m * 16 + g, lr1 = lr0 + 8;
    const bool ok0 = row0 < nrows, ok1 = row1 < nrows;
    const float2* R2 = (const float2*)resid;
    float s0 = 0.f, q0 = 0.f, s1 = 0.f, q1 = 0.f;
    #pragma unroll
    for (int q = 0; q < 8; q++) {
        int col = (wid_n * 8 + q) * 8 + t * 2;
        float2 b2 = *(const float2*)(b2_s + col);
        float2 r0 = ok0 ? R2[(size_t)row0 * 64 + (col >> 1)] : make_float2(0.f, 0.f);
        float2 r1 = ok1 ? R2[(size_t)row1 * 64 + (col >> 1)] : make_float2(0.f, 0.f);
        float v00 = fmaxf(c[q][0] + b2.x, 0.f) + r0.x;
        float v01 = fmaxf(c[q][1] + b2.y, 0.f) + r0.y;
        float v10 = fmaxf(c[q][2] + b2.x, 0.f) + r1.x;
        float v11 = fmaxf(c[q][3] + b2.y, 0.f) + r1.y;
        c[q][0] = v00; c[q][1] = v01; c[q][2] = v10; c[q][3] = v11;
        s0 += v00 + v01; q0 += v00 * v00 + v01 * v01;
        s1 += v10 + v11; q1 += v10 * v10 + v11 * v11;
    }
    #pragma unroll
    for (int off = 1; off <= 2; off <<= 1) {
        s0 += __shfl_xor_sync(0xFFFFFFFFu, s0, off);
        q0 += __shfl_xor_sync(0xFFFFFFFFu, q0, off);
        s1 += __shfl_xor_sync(0xFFFFFFFFu, s1, off);
        q1 += __shfl_xor_sync(0xFFFFFFFFu, q1, off);
    }
    if (t == 0) {
        red[lr0 * 2 + wid_n] = make_float2(s0, q0);
        red[lr1 * 2 + wid_n] = make_float2(s1, q1);
    }
    __syncthreads();
    {
        float2 a0 = red[lr0 * 2 + 0], a1 = red[lr0 * 2 + 1];
        float2 c0 = red[lr1 * 2 + 0], c1 = red[lr1 * 2 + 1];
        s0 = a0.x + a1.x; q0 = a0.y + a1.y;
        s1 = c0.x + c1.x; q1 = c0.y + c1.y;
    }
    float mean0 = s0 * (1.0f / D_DIM);
    float mean1 = s1 * (1.0f / D_DIM);
    float rstd0 = rsqrtf(q0 * (1.0f / D_DIM) - mean0 * mean0 + LN_EPS);
    float rstd1 = rsqrtf(q1 * (1.0f / D_DIM) - mean1 * mean1 + LN_EPS);
    float2* out2 = (float2*)out;
    #pragma unroll
    for (int q = 0; q < 8; q++) {
        int col = (wid_n * 8 + q) * 8 + t * 2;
        float2 g2 = *(const float2*)(gm_s + col);
        float2 t2 = *(const float2*)(bt_s + col);
        if (ok0) {
            float2 o;
            o.x = (c[q][0] - mean0) * rstd0 * g2.x + t2.x;
            o.y = (c[q][1] - mean0) * rstd0 * g2.y + t2.y;
            out2[(size_t)row0 * 64 + (col >> 1)] = o;
        }
        if (ok1) {
            float2 o;
            o.x = (c[q][2] - mean1) * rstd1 * g2.x + t2.x;
            o.y = (c[q][3] - mean1) * rstd1 * g2.y + t2.y;
            out2[(size_t)row1 * 64 + (col >> 1)] = o;
        }
    }
}

// ---------------------------------------------------------------------------
extern "C" void kernel_launch(void* const* d_in, const int* in_sizes, int n_in,
                              void* d_out, int out_size) {
    const float* h     = (const float*)d_in[0];
    const int*   src   = (const int*)  d_in[1];
    const int*   dst   = (const int*)  d_in[2];
    const float* W_pre = (const float*)d_in[3];
    const float* b_pre = (const float*)d_in[4];
    const float* W1    = (const float*)d_in[5];
    const float* b1    = (const float*)d_in[6];
    const float* W2    = (const float*)d_in[7];
    const float* b2    = (const float*)d_in[8];
    const float* gamma = (const float*)d_in[9];
    const float* beta  = (const float*)d_in[10];
    float* out = (float*)d_out;

    float *hpre, *agg;
    uint4* bf;
    cudaGetSymbolAddress((void**)&hpre, g_hpre);
    cudaGetSymbolAddress((void**)&agg,  g_agg);
    cudaGetSymbolAddress((void**)&bf,   g_bfrag);
    const uint4* bf_pre = bf;
    const uint4* bf_w1  = bf + 4096;
    const uint4* bf_w2  = bf + 8192;

    cudaFuncSetAttribute(gemm_pre, cudaFuncAttributeMaxDynamicSharedMemorySize, SMEM_TOTAL);
    cudaFuncSetAttribute(gemm_mlp, cudaFuncAttributeMaxDynamicSharedMemorySize, SMEM_TOTAL);

    const int blocks = (N_NODES + TILE_M - 1) / TILE_M;  // 782
    const int eblk   = (N_EDGES + 255) / 256;            // 2344

    // CSR build (independent of weights)
    zero_cnt_kernel<<<196, 256>>>();
    hist_kernel<<<eblk, 256>>>(dst);
    bsum_kernel<<<196, 256>>>();
    offs_kernel<<<196, 256>>>();
    fill_kernel<<<eblk, 256>>>(src, dst);
    // Weights + pre-projection
    wprep_kernel<<<24, 256>>>(W_pre, W1, W2);
    gemm_pre<<<blocks, NT, SMEM_TOTAL>>>(h, b_pre, bf_pre, hpre, N_NODES);
    // agg[n] = sum of hpre[src] over in-edges (no atomics)
    gather_kernel<<<(N_NODES * 32 + 255) / 256, 256>>>(hpre, agg);
    // Fused MLP + residual + LayerNorm
    gemm_mlp<<<blocks, NT, SMEM_TOTAL>>>(agg, b1, b2, bf_w1, bf_w2,
                                         hpre, gamma, beta, out, N_NODES);
    (void)in_sizes; (void)n_in; (void)out_size;
}